// round 1
// baseline (speedup 1.0000x reference)
#include <cuda_runtime.h>
#include <math.h>

#define B_  2
#define S_  2048
#define D_  1024
#define H_  16
#define HD_ 64
#define M_  (B_ * S_)   // 4096

// Scratch (device globals: allocation inside kernel_launch is forbidden).
// q/k/v stored as [B, H, S, HD]; ctx as [B, S, D].
__device__ float g_q[B_ * H_ * S_ * HD_];
__device__ float g_k[B_ * H_ * S_ * HD_];
__device__ float g_v[B_ * H_ * S_ * HD_];
__device__ float g_ctx[B_ * S_ * D_];

// ---------------------------------------------------------------------------
// Tiled SGEMM: C[M,1024] = A[M,1024] @ W[1024,1024] + bias
// BM=BN=128, BK=16, 256 threads, 8x8 register tile per thread.
// SPLIT=true: write with head-split layout [B,H,S,HD]; else plain row-major.
// ---------------------------------------------------------------------------
template <bool SPLIT>
__global__ __launch_bounds__(256) void gemm_kernel(
    const float* __restrict__ A, const float* __restrict__ W,
    const float* __restrict__ bias, float* __restrict__ out)
{
    __shared__ float As[16][132];   // A tile, transposed: As[k][m]
    __shared__ float Bs[16][128];   // W tile: Bs[k][n]

    const int t   = threadIdx.x;
    const int tx  = t & 15;
    const int ty  = t >> 4;
    const int n0  = blockIdx.x * 128;
    const int row0 = blockIdx.y * 128;

    float acc[8][8];
#pragma unroll
    for (int i = 0; i < 8; i++)
#pragma unroll
        for (int j = 0; j < 8; j++) acc[i][j] = 0.f;

    for (int k0 = 0; k0 < D_; k0 += 16) {
#pragma unroll
        for (int l = 0; l < 2; l++) {
            int idx = t + l * 256;
            // A tile: 128 rows x 16 cols, 512 float4s
            int ar = idx >> 2, ac4 = idx & 3;
            float4 av4 = *(const float4*)&A[(size_t)(row0 + ar) * D_ + k0 + ac4 * 4];
            As[ac4 * 4 + 0][ar] = av4.x;
            As[ac4 * 4 + 1][ar] = av4.y;
            As[ac4 * 4 + 2][ar] = av4.z;
            As[ac4 * 4 + 3][ar] = av4.w;
            // W tile: 16 rows x 128 cols, 512 float4s
            int kr = idx >> 5, bc4 = idx & 31;
            *(float4*)&Bs[kr][bc4 * 4] =
                *(const float4*)&W[(size_t)(k0 + kr) * D_ + n0 + bc4 * 4];
        }
        __syncthreads();

#pragma unroll
        for (int k = 0; k < 16; k++) {
            float av[8], bv[8];
            *(float4*)&av[0] = *(const float4*)&As[k][ty * 8];
            *(float4*)&av[4] = *(const float4*)&As[k][ty * 8 + 4];
            *(float4*)&bv[0] = *(const float4*)&Bs[k][tx * 8];
            *(float4*)&bv[4] = *(const float4*)&Bs[k][tx * 8 + 4];
#pragma unroll
            for (int i = 0; i < 8; i++)
#pragma unroll
                for (int j = 0; j < 8; j++)
                    acc[i][j] += av[i] * bv[j];
        }
        __syncthreads();
    }

#pragma unroll
    for (int i = 0; i < 8; i++) {
        int row = row0 + ty * 8 + i;
#pragma unroll
        for (int j = 0; j < 8; j++) {
            int col = n0 + tx * 8 + j;
            float v = acc[i][j] + bias[col];
            if (SPLIT) {
                int b = row >> 11;           // row / S_
                int s = row & (S_ - 1);
                int h = col >> 6;            // col / HD_
                int hd = col & 63;
                out[(((size_t)(b * H_ + h)) * S_ + s) * HD_ + hd] = v;
            } else {
                out[(size_t)row * D_ + col] = v;
            }
        }
    }
}

// ---------------------------------------------------------------------------
// Flash-attention: one block = 64 queries of one (b,h). 256 threads as 16x16,
// 4x4 micro-tile per thread. K tile stored transposed + XOR-swizzled so the
// QK^T inner loop is conflict-free LDS.128. P reuses the K buffer.
// Dynamic smem: Qs[64][68] + Vs[64][68] + KP[64*68] = 52224 bytes.
// ---------------------------------------------------------------------------
__global__ __launch_bounds__(256) void attn_kernel()
{
    extern __shared__ float smx[];
    float* Qs = smx;                 // [64][68]
    float* Vs = smx + 64 * 68;       // [64][68]
    float* KP = smx + 2 * 64 * 68;   // Kt [64][64] swizzled, then Ps [64][68]

    const int t  = threadIdx.x;
    const int tx = t & 15;
    const int ty = t >> 4;
    const int q0 = blockIdx.x * 64;
    const int bh = blockIdx.y;       // b*H + h
    const size_t base = (size_t)bh * S_ * HD_;
    const float* Qg = g_q + base;
    const float* Kg = g_k + base;
    const float* Vg = g_v + base;

    // Q tile (pre-scaled by 1/sqrt(HD) = 0.125)
#pragma unroll
    for (int l = 0; l < 4; l++) {
        int idx = t + l * 256;       // 1024 float4s
        int r = idx >> 4, c4 = idx & 15;
        float4 v = *(const float4*)&Qg[(size_t)(q0 + r) * HD_ + c4 * 4];
        v.x *= 0.125f; v.y *= 0.125f; v.z *= 0.125f; v.w *= 0.125f;
        *(float4*)&Qs[r * 68 + c4 * 4] = v;
    }

    float m_i[4], l_i[4], o[4][4];
#pragma unroll
    for (int i = 0; i < 4; i++) {
        m_i[i] = -1e30f;
        l_i[i] = 0.f;
#pragma unroll
        for (int j = 0; j < 4; j++) o[i][j] = 0.f;
    }
    __syncthreads();

    for (int kt = 0; kt < S_ / 64; kt++) {
        const int k0 = kt * 64;
        // Load K (transposed + swizzled) and V (row-major)
#pragma unroll
        for (int l = 0; l < 4; l++) {
            int idx = t + l * 256;
            int r = idx >> 4, c4 = idx & 15;
            float4 kv = *(const float4*)&Kg[(size_t)(k0 + r) * HD_ + c4 * 4];
            int pos = (((r >> 2) ^ c4) << 2) + (r & 3);   // swizzle on key-group
            KP[(c4 * 4 + 0) * 64 + pos] = kv.x;
            KP[(c4 * 4 + 1) * 64 + pos] = kv.y;
            KP[(c4 * 4 + 2) * 64 + pos] = kv.z;
            KP[(c4 * 4 + 3) * 64 + pos] = kv.w;
            *(float4*)&Vs[r * 68 + c4 * 4] =
                *(const float4*)&Vg[(size_t)(k0 + r) * HD_ + c4 * 4];
        }
        __syncthreads();

        // S = Q @ K^T   (thread: rows ty*4+i, keys tx*4+j)
        float s[4][4];
#pragma unroll
        for (int i = 0; i < 4; i++)
#pragma unroll
            for (int j = 0; j < 4; j++) s[i][j] = 0.f;

#pragma unroll
        for (int dd = 0; dd < 64; dd += 4) {
            int sw = ((tx ^ (dd >> 2)) << 2);
            float4 b0 = *(const float4*)&KP[(dd + 0) * 64 + sw];
            float4 b1 = *(const float4*)&KP[(dd + 1) * 64 + sw];
            float4 b2 = *(const float4*)&KP[(dd + 2) * 64 + sw];
            float4 b3 = *(const float4*)&KP[(dd + 3) * 64 + sw];
#pragma unroll
            for (int i = 0; i < 4; i++) {
                float4 a = *(const float4*)&Qs[(ty * 4 + i) * 68 + dd];
                s[i][0] += a.x * b0.x + a.y * b1.x + a.z * b2.x + a.w * b3.x;
                s[i][1] += a.x * b0.y + a.y * b1.y + a.z * b2.y + a.w * b3.y;
                s[i][2] += a.x * b0.z + a.y * b1.z + a.z * b2.z + a.w * b3.z;
                s[i][3] += a.x * b0.w + a.y * b1.w + a.z * b2.w + a.w * b3.w;
            }
        }
        __syncthreads();   // all reads of KP-as-Kt done before P overwrites it

        // Online softmax. Row group = 16 lanes (tx); shfl width-16 reductions.
#pragma unroll
        for (int i = 0; i < 4; i++) {
            float mx = fmaxf(fmaxf(s[i][0], s[i][1]), fmaxf(s[i][2], s[i][3]));
            mx = fmaxf(mx, __shfl_xor_sync(0xffffffffu, mx, 1));
            mx = fmaxf(mx, __shfl_xor_sync(0xffffffffu, mx, 2));
            mx = fmaxf(mx, __shfl_xor_sync(0xffffffffu, mx, 4));
            mx = fmaxf(mx, __shfl_xor_sync(0xffffffffu, mx, 8));
            float mnew = fmaxf(m_i[i], mx);
            float corr = __expf(m_i[i] - mnew);
            float rs = 0.f;
#pragma unroll
            for (int j = 0; j < 4; j++) {
                s[i][j] = __expf(s[i][j] - mnew);
                rs += s[i][j];
            }
            rs += __shfl_xor_sync(0xffffffffu, rs, 1);
            rs += __shfl_xor_sync(0xffffffffu, rs, 2);
            rs += __shfl_xor_sync(0xffffffffu, rs, 4);
            rs += __shfl_xor_sync(0xffffffffu, rs, 8);
            l_i[i] = l_i[i] * corr + rs;
            m_i[i] = mnew;
#pragma unroll
            for (int j = 0; j < 4; j++) o[i][j] *= corr;
        }

        // P -> smem (reuse KP, pitch 68)
        float* Ps = KP;
#pragma unroll
        for (int i = 0; i < 4; i++)
            *(float4*)&Ps[(ty * 4 + i) * 68 + tx * 4] =
                make_float4(s[i][0], s[i][1], s[i][2], s[i][3]);
        __syncthreads();

        // O += P @ V   (thread: rows ty*4+i, dims tx*4+j)
#pragma unroll
        for (int kk = 0; kk < 64; kk += 4) {
            float4 v0 = *(const float4*)&Vs[(kk + 0) * 68 + tx * 4];
            float4 v1 = *(const float4*)&Vs[(kk + 1) * 68 + tx * 4];
            float4 v2 = *(const float4*)&Vs[(kk + 2) * 68 + tx * 4];
            float4 v3 = *(const float4*)&Vs[(kk + 3) * 68 + tx * 4];
#pragma unroll
            for (int i = 0; i < 4; i++) {
                float4 p = *(const float4*)&Ps[(ty * 4 + i) * 68 + kk];
                o[i][0] += p.x * v0.x + p.y * v1.x + p.z * v2.x + p.w * v3.x;
                o[i][1] += p.x * v0.y + p.y * v1.y + p.z * v2.y + p.w * v3.y;
                o[i][2] += p.x * v0.z + p.y * v1.z + p.z * v2.z + p.w * v3.z;
                o[i][3] += p.x * v0.w + p.y * v1.w + p.z * v2.w + p.w * v3.w;
            }
        }
        __syncthreads();   // before next tile overwrites KP/Vs
    }

    // ctx[b, s, h*64 + d] = O / l
    const int b = bh >> 4;
    const int h = bh & 15;
#pragma unroll
    for (int i = 0; i < 4; i++) {
        float inv = 1.f / l_i[i];
        int srow = q0 + ty * 4 + i;
        *(float4*)&g_ctx[((size_t)(b * S_ + srow)) * D_ + h * HD_ + tx * 4] =
            make_float4(o[i][0] * inv, o[i][1] * inv, o[i][2] * inv, o[i][3] * inv);
    }
}

// ---------------------------------------------------------------------------

extern "C" void kernel_launch(void* const* d_in, const int* in_sizes, int n_in,
                              void* d_out, int out_size)
{
    const float* x  = (const float*)d_in[0];
    const float* Wq = (const float*)d_in[1];
    const float* bq = (const float*)d_in[2];
    const float* Wk = (const float*)d_in[3];
    const float* bk = (const float*)d_in[4];
    const float* Wv = (const float*)d_in[5];
    const float* bv = (const float*)d_in[6];
    const float* Wo = (const float*)d_in[7];
    const float* bo = (const float*)d_in[8];
    float* out = (float*)d_out;

    float *qp, *kp, *vp, *cp;
    cudaGetSymbolAddress((void**)&qp, g_q);
    cudaGetSymbolAddress((void**)&kp, g_k);
    cudaGetSymbolAddress((void**)&vp, g_v);
    cudaGetSymbolAddress((void**)&cp, g_ctx);

    const int ATTN_SMEM = 3 * 64 * 68 * (int)sizeof(float);   // 52224 B
    cudaFuncSetAttribute(attn_kernel,
                         cudaFuncAttributeMaxDynamicSharedMemorySize, ATTN_SMEM);

    dim3 gg(D_ / 128, M_ / 128);   // (8, 32)
    gemm_kernel<true ><<<gg, 256>>>(x,  Wq, bq, qp);
    gemm_kernel<true ><<<gg, 256>>>(x,  Wk, bk, kp);
    gemm_kernel<true ><<<gg, 256>>>(x,  Wv, bv, vp);
    attn_kernel<<<dim3(S_ / 64, B_ * H_), 256, ATTN_SMEM>>>();
    gemm_kernel<false><<<gg, 256>>>(cp, Wo, bo, out);
}